// round 2
// baseline (speedup 1.0000x reference)
#include <cuda_runtime.h>

#define NBOX   4096
#define NBATCH 16
#define MAXP   300
#define BT     512
#define W0     512          // greedy window (16 bits/lane in warp 0)
#define NC     (W0 / 32)    // candidates per lane in window
#define IOU_T  0.7f
#define SC_T   0.5f
#define FULLM  0xffffffffu

typedef unsigned long long ull;

struct Smem {
    ull    sk[NBOX];        // sort key: (~orderable(score))<<32 | idx ; ascending
    float4 box[NBOX];       // x1,y1,x2,y2 in sorted order
    float  area[NBOX];
    unsigned char sup[NBOX];
    int    kept[MAXP];
    int    nk;
    int    need_fb;
};

// Decide fl_div(inter,denom) >= 0.7 exactly. Guard band 2e-6 rel covers the
// <=3*2^-24 accumulated rounding of td and the division; exact div in-band.
__device__ __forceinline__ bool iou_ge(float4 a, float aa, float4 b, float ab) {
    float xx1 = fmaxf(a.x, b.x);
    float yy1 = fmaxf(a.y, b.y);
    float xx2 = fminf(a.z, b.z);
    float yy2 = fminf(a.w, b.w);
    float w = fmaxf(__fadd_rn(xx2, -xx1), 0.0f);
    float h = fmaxf(__fadd_rn(yy2, -yy1), 0.0f);
    float inter = __fmul_rn(w, h);
    float denom = __fadd_rn(__fadd_rn(aa, ab), -inter);
    float td = __fmul_rn(IOU_T, denom);
    if (inter > __fmul_rn(td, 1.000002f)) return true;
    if (inter < __fmul_rn(td, 0.999998f)) return false;
    return __fdiv_rn(inter, denom) >= IOU_T;
}

__global__ __launch_bounds__(BT, 1)
void nms_kernel(const float4* __restrict__ props,   // [B,N,4]
                const float2* __restrict__ cls,     // [B,N,2]
                float* __restrict__ outb,           // [B,300,4]
                float* __restrict__ outs)           // [B,300]
{
    extern __shared__ unsigned char smem_raw[];
    Smem& s = *reinterpret_cast<Smem*>(smem_raw);

    const int b   = blockIdx.x;
    const int tid = threadIdx.x;
    const float4* P = props + (size_t)b * NBOX;
    const float2* C = cls   + (size_t)b * NBOX;

    // ---- keys: descending score, ascending index, invalid last (stable) ----
    for (int t = tid; t < NBOX; t += BT) {
        float sc = C[t].y;
        unsigned u = (sc > SC_T) ? ~(__float_as_uint(sc) | 0x80000000u)
                                 : 0xFF800000u;
        s.sk[t] = ((ull)u << 32) | (unsigned)t;
    }
    __syncthreads();

    // ---- bitonic sort over comparator indices (2048 CEs/pass) ----
    for (int k = 2; k <= NBOX; k <<= 1) {
        for (int j = k >> 1; j > 0; j >>= 1) {
            for (int c = tid; c < NBOX / 2; c += BT) {
                int t   = ((c & ~(j - 1)) << 1) | (c & (j - 1));
                int u2  = t | j;
                ull A = s.sk[t], Bk = s.sk[u2];
                bool up = ((t & k) == 0);
                if ((A > Bk) == up) { s.sk[t] = Bk; s.sk[u2] = A; }
            }
            __syncthreads();
        }
    }

    // ---- gather window0 candidates ----
    if (tid < W0) {
        ull key = s.sk[tid];
        int oi = (int)(key & 0xffffffffu);
        float4 p = P[oi];
        s.box[tid]  = p;
        s.area[tid] = __fmul_rn(__fadd_rn(p.z, -p.x), __fadd_rn(p.w, -p.y));
        s.sup[tid]  = ((unsigned)(key >> 32) == 0xFF800000u) ? 1 : 0;
    }
    if (tid == 0) { s.nk = 0; s.need_fb = 0; }
    __syncthreads();

    // ---- warp-synchronous greedy over window0 (no block barriers) ----
    if (tid < 32) {
        const int lane = tid;
        unsigned supm = 0;                      // bit c: j = c*32+lane suppressed
        for (int c = 0; c < NC; ++c)
            supm |= (unsigned)s.sup[c * 32 + lane] << c;

        int nk = 0;
        bool filled = false;
        for (int blk = 0; blk < NC && !filled; ++blk) {
            unsigned alive = __ballot_sync(FULLM, !((supm >> blk) & 1));
            while (alive) {
                int t = __ffs(alive) - 1;
                int i = blk * 32 + t;
                if (lane == 0) s.kept[nk] = i;
                nk++;
                float4 bi = s.box[i];           // broadcast smem read
                float  ai = s.area[i];
                for (int c = i >> 5; c < NC; ++c) {
                    int j = c * 32 + lane;
                    if (j > i && !((supm >> c) & 1)) {
                        if (iou_ge(bi, ai, s.box[j], s.area[j]))
                            supm |= 1u << c;
                    }
                }
                if (nk == MAXP) { filled = true; break; }
                alive &= alive - 1;             // drop i itself
                alive &= __ballot_sync(FULLM, !((supm >> blk) & 1));
            }
        }
        if (lane == 0) { s.nk = nk; s.need_fb = (nk < MAXP) ? 1 : 0; }
        if (nk < MAXP)                          // dump state for fallback
            for (int c = 0; c < NC; ++c)
                s.sup[c * 32 + lane] = (supm >> c) & 1;
    }
    __syncthreads();

    // ---- fallback: extend window to full list (rare; exact) ----
    if (s.need_fb) {
        for (int t = W0 + tid; t < NBOX; t += BT) {
            ull key = s.sk[t];
            int oi = (int)(key & 0xffffffffu);
            float4 p = P[oi];
            s.box[t]  = p;
            s.area[t] = __fmul_rn(__fadd_rn(p.z, -p.x), __fadd_rn(p.w, -p.y));
            s.sup[t]  = ((unsigned)(key >> 32) == 0xFF800000u) ? 1 : 0;
        }
        __syncthreads();
        // apply already-kept boxes to the new region (order irrelevant: OR)
        int nk0 = s.nk;
        for (int t = W0 + tid; t < NBOX; t += BT) {
            if (s.sup[t]) continue;
            float4 bj = s.box[t]; float aj = s.area[t];
            unsigned char sp = 0;
            for (int k2 = 0; k2 < nk0; ++k2) {
                int i = s.kept[k2];
                if (iou_ge(s.box[i], s.area[i], bj, aj)) { sp = 1; break; }
            }
            s.sup[t] = sp;
        }
        __syncthreads();
        // continue serial greedy from i = W0
        for (int i = W0; i < NBOX; ++i) {
            if (s.nk >= MAXP) break;            // uniform: nk changes under barrier
            if (s.sup[i]) continue;             // uniform: finalized earlier
            if (tid == 0) s.kept[s.nk] = i;
            float4 bi = s.box[i]; float ai = s.area[i];
            for (int j = i + 1 + tid; j < NBOX; j += BT) {
                if (s.sup[j]) continue;
                if (iou_ge(bi, ai, s.box[j], s.area[j])) s.sup[j] = 1;
            }
            __syncthreads();
            if (tid == 0) s.nk++;
            __syncthreads();
        }
    }
    __syncthreads();

    // ---- emit: first min(nk,300) kept in score order, pad with last kept ----
    int nk  = s.nk;
    int pad = (nk > 0) ? s.kept[nk - 1] : (NBOX - 1);   // nk==0 -> order[N-1]
    for (int t = tid; t < MAXP; t += BT) {
        int pos = (t < nk) ? s.kept[t] : pad;
        int oi  = (int)(s.sk[pos] & 0xffffffffu);
        reinterpret_cast<float4*>(outb)[b * MAXP + t] = P[oi];
        outs[b * MAXP + t] = C[oi].y;
    }
}

extern "C" void kernel_launch(void* const* d_in, const int* in_sizes, int n_in,
                              void* d_out, int out_size)
{
    const float4* props = (const float4*)d_in[0];
    const float2* cls   = (const float2*)d_in[1];
    float* outb = (float*)d_out;                          // [16,300,4]
    float* outs = (float*)d_out + NBATCH * MAXP * 4;      // [16,300]

    cudaFuncSetAttribute(nms_kernel,
                         cudaFuncAttributeMaxDynamicSharedMemorySize,
                         (int)sizeof(Smem));
    nms_kernel<<<NBATCH, BT, sizeof(Smem)>>>(props, cls, outb, outs);
}

// round 3
// speedup vs baseline: 3.6811x; 3.6811x over previous
#include <cuda_runtime.h>

#define NB    16
#define NN    4096
#define W     1024
#define MAXP  300
#define IOU_T 0.7f
#define SC_T  0.5f
#define SENT  0xFF800000u
#define FULLM 0xffffffffu

typedef unsigned long long ull;

// Inter-kernel scratch (static __device__ arrays: allowed, no allocation)
__device__ ull      g_keys[NB][NN];
__device__ float4   g_box [NB][W];
__device__ float    g_area[NB][W];
__device__ unsigned g_mask[NB][W][32];   // 2 MB: row i, word w -> bits for j = w*32+b

// Exact decision fdiv_rn(inter,denom) >= 0.7 via guard band (band 2e-6 rel >>
// accumulated <=3*2^-24 rounding of 0.7*denom and the division; exact div in band).
__device__ __forceinline__ bool iou_ge(float4 a, float aa, float4 b, float ab) {
    float xx1 = fmaxf(a.x, b.x);
    float yy1 = fmaxf(a.y, b.y);
    float xx2 = fminf(a.z, b.z);
    float yy2 = fminf(a.w, b.w);
    float w = fmaxf(__fadd_rn(xx2, -xx1), 0.0f);
    float h = fmaxf(__fadd_rn(yy2, -yy1), 0.0f);
    float inter = __fmul_rn(w, h);
    float denom = __fadd_rn(__fadd_rn(aa, ab), -inter);
    float td = __fmul_rn(IOU_T, denom);
    if (inter > __fmul_rn(td, 1.000002f)) return true;
    if (inter < __fmul_rn(td, 0.999998f)) return false;
    return __fdiv_rn(inter, denom) >= IOU_T;
}

// ---------------- K1: per-image key build + bitonic sort -------------------
__global__ __launch_bounds__(1024, 1)
void k_sort(const float4* __restrict__ props, const float2* __restrict__ cls)
{
    __shared__ ull sk[NN];
    const int b   = blockIdx.x;
    const int tid = threadIdx.x;
    const float4* P = props + (size_t)b * NN;
    const float2* C = cls   + (size_t)b * NN;

    for (int t = tid; t < NN; t += 1024) {
        float sc = C[t].y;
        unsigned u = (sc > SC_T) ? ~(__float_as_uint(sc) | 0x80000000u) : SENT;
        sk[t] = ((ull)u << 32) | (unsigned)t;
    }
    __syncthreads();

    for (int k = 2; k <= NN; k <<= 1) {
        for (int j = k >> 1; j > 0; j >>= 1) {
            for (int c = tid; c < NN / 2; c += 1024) {
                int t  = ((c & ~(j - 1)) << 1) | (c & (j - 1));
                int u2 = t | j;
                ull A = sk[t], Bk = sk[u2];
                bool up = ((t & k) == 0);
                if ((A > Bk) == up) { sk[t] = Bk; sk[u2] = A; }
            }
            __syncthreads();
        }
    }

    for (int t = tid; t < NN; t += 1024) g_keys[b][t] = sk[t];
    // gather window boxes in sorted order
    {
        int t = tid;  // 1024 threads == W
        int oi = (int)(sk[t] & 0xffffffffu);
        float4 p = P[oi];
        g_box[b][t]  = p;
        g_area[b][t] = __fmul_rn(__fadd_rn(p.z, -p.x), __fadd_rn(p.w, -p.y));
    }
}

// ---------------- K2: suppression bit-matrix (16 images x 8 slices) --------
__global__ __launch_bounds__(1024, 1)
void k_mask()
{
    __shared__ float4 sb[W];
    __shared__ float  sa[W];
    const int b   = blockIdx.x;
    const int s   = blockIdx.y;          // 0..7 slice
    const int tid = threadIdx.x;

    for (int t = tid; t < W; t += 1024) { sb[t] = g_box[b][t]; sa[t] = g_area[b][t]; }
    __syncthreads();

    // 128 rows per CTA, interleaved 16-row groups for load balance
    const int r  = tid >> 3;                       // 0..127
    const int wq = tid & 7;                        // 0..7
    const int i  = ((r >> 4) * 8 + s) * 16 + (r & 15);
    const float4 bi = sb[i];
    const float  ai = sa[i];
    const int wlo = i >> 5;

    #pragma unroll
    for (int p = 0; p < 4; ++p) {
        int w = wq * 4 + p;
        unsigned bits = 0;
        if (w >= wlo) {
            #pragma unroll 8
            for (int bb = 0; bb < 32; ++bb) {
                int j = w * 32 + bb;
                if (iou_ge(bi, ai, sb[j], sa[j])) bits |= 1u << bb;
            }
            if (w == wlo) bits &= ~((2u << (i & 31)) - 1);   // keep only j > i
        }
        g_mask[b][i][w] = bits;                               // w<wlo rows must be 0
    }
}

// ---------------- K3: warp scan + exact fallback + emit --------------------
__global__ __launch_bounds__(1024, 1)
void k_scan(const float4* __restrict__ props, const float2* __restrict__ cls,
            float* __restrict__ outb, float* __restrict__ outs)
{
    extern __shared__ unsigned char sm[];
    unsigned* s_mask = (unsigned*)sm;                          // 131072 B
    ull*      s_sk   = (ull*)   (sm + 131072);                 //  32768 B
    float4*   s_box  = (float4*)(sm + 131072 + 32768);         //  16384 B
    float*    s_area = (float*) (sm + 131072 + 32768 + 16384); //   4096 B
    float4*   s_kbox = (float4*)(sm + 184320);                 //   4800 B
    float*    s_kar  = (float*) (sm + 189120);                 //   1200 B
    int*      s_kept = (int*)   (sm + 190320);                 //   1200 B
    unsigned* s_inv  = (unsigned*)(sm + 191520);               //    128 B
    int*      s_ctl  = (int*)   (sm + 191648);
    // fallback chunk arrays alias the (finished) mask region
    float4*        c_box  = (float4*)sm;                       // 16384 B
    float*         c_area = (float*)(sm + 16384);              //  4096 B
    unsigned char* c_sup  = (unsigned char*)(sm + 20480);      //  1024 B

    const int b   = blockIdx.x;
    const int tid = threadIdx.x;
    const int lane = tid & 31, wid = tid >> 5;
    const float4* P = props + (size_t)b * NN;
    const float2* C = cls   + (size_t)b * NN;

    // stage mask + keys + window boxes into smem
    {
        const uint4* gm = (const uint4*)g_mask[b];
        uint4* smv = (uint4*)s_mask;
        for (int t = tid; t < 8192; t += 1024) smv[t] = gm[t];
        for (int t = tid; t < NN;  t += 1024) s_sk[t] = g_keys[b][t];
        s_box[tid]  = g_box[b][tid];
        s_area[tid] = g_area[b][tid];
    }
    __syncthreads();
    // invalid bits, one 32-bit word per warp
    {
        bool iv = ((unsigned)(s_sk[tid] >> 32) == SENT);
        unsigned bal = __ballot_sync(FULLM, iv);
        if (lane == 0) s_inv[wid] = bal;
    }
    __syncthreads();

    // ---- warp 0: greedy scan over window via bitmask rows ----
    if (tid < 32) {
        unsigned r = s_inv[lane];       // lane owns removed bits [32*lane, 32*lane+32)
        int nk = 0; bool done = false;
        for (int blk = 0; blk < 32 && !done; ++blk) {
            unsigned alive = ~__shfl_sync(FULLM, r, blk);
            while (alive) {
                int t2 = __ffs(alive) - 1;
                int i  = blk * 32 + t2;
                if (lane == 0) s_kept[nk] = i;
                nk++;
                if (nk == MAXP) { done = true; break; }
                r |= s_mask[i * 32 + lane];
                alive &= ~(1u << t2);
                alive &= ~__shfl_sync(FULLM, r, blk);
            }
        }
        if (lane == 0) s_ctl[0] = nk;
    }
    __syncthreads();

    // record kept boxes for (rare) fallback prefilter
    {
        int nk = s_ctl[0];
        for (int t = tid; t < nk; t += 1024) {
            int pos = s_kept[t];
            s_kbox[t] = s_box[pos];
            s_kar[t]  = s_area[pos];
        }
    }
    __syncthreads();

    // ---- exact fallback beyond the window (rare) ----
    for (int c = 1; c < 4; ++c) {
        int nk0 = s_ctl[0];
        if (nk0 >= MAXP) break;                    // uniform
        {
            int jg = c * 1024 + tid;
            ull key = s_sk[jg];
            int oi = (int)(key & 0xffffffffu);
            float4 pb = P[oi];
            float  pa = __fmul_rn(__fadd_rn(pb.z, -pb.x), __fadd_rn(pb.w, -pb.y));
            unsigned char sp = ((unsigned)(key >> 32) == SENT) ? 1 : 0;
            if (!sp) {
                for (int k2 = 0; k2 < nk0; ++k2)
                    if (iou_ge(s_kbox[k2], s_kar[k2], pb, pa)) { sp = 1; break; }
            }
            c_box[tid] = pb; c_area[tid] = pa; c_sup[tid] = sp;
        }
        __syncthreads();
        if (tid < 32) {
            unsigned supm = 0;                      // bit w: local j = w*32+lane
            for (int w = 0; w < 32; ++w)
                supm |= (unsigned)c_sup[w * 32 + lane] << w;
            int nk = nk0; bool done2 = false;
            for (int blk = 0; blk < 32 && !done2; ++blk) {
                unsigned alive = __ballot_sync(FULLM, !((supm >> blk) & 1));
                while (alive) {
                    int t2 = __ffs(alive) - 1;
                    int li = blk * 32 + t2;
                    float4 bb = c_box[li]; float ba = c_area[li];
                    if (lane == 0) {
                        s_kept[nk] = c * 1024 + li;
                        s_kbox[nk] = bb; s_kar[nk] = ba;
                    }
                    nk++;
                    if (nk == MAXP) { done2 = true; break; }
                    for (int w = blk; w < 32; ++w) {
                        int j = w * 32 + lane;
                        if (j > li && !((supm >> w) & 1)) {
                            if (iou_ge(bb, ba, c_box[j], c_area[j])) supm |= 1u << w;
                        }
                    }
                    alive &= ~(1u << t2);
                    alive &= __ballot_sync(FULLM, !((supm >> blk) & 1));
                }
            }
            if (lane == 0) s_ctl[0] = nk;
        }
        __syncthreads();
    }

    // ---- emit ----
    {
        int nk  = s_ctl[0];
        int pad = (nk > 0) ? s_kept[nk - 1] : (NN - 1);
        for (int t = tid; t < MAXP; t += 1024) {
            int pos = (t < nk) ? s_kept[t] : pad;
            int oi  = (int)(s_sk[pos] & 0xffffffffu);
            reinterpret_cast<float4*>(outb)[b * MAXP + t] = P[oi];
            outs[b * MAXP + t] = C[oi].y;
        }
    }
}

extern "C" void kernel_launch(void* const* d_in, const int* in_sizes, int n_in,
                              void* d_out, int out_size)
{
    const float4* props = (const float4*)d_in[0];
    const float2* cls   = (const float2*)d_in[1];
    float* outb = (float*)d_out;                          // [16,300,4]
    float* outs = (float*)d_out + NB * MAXP * 4;          // [16,300]

    static int smem_set = 0;
    const int K3_SMEM = 191664;
    if (!smem_set) {
        cudaFuncSetAttribute(k_scan, cudaFuncAttributeMaxDynamicSharedMemorySize, K3_SMEM);
        smem_set = 1;
    }
    k_sort<<<NB, 1024>>>(props, cls);
    k_mask<<<dim3(NB, 8), 1024>>>();
    k_scan<<<NB, 1024, K3_SMEM>>>(props, cls, outb, outs);
}

// round 4
// speedup vs baseline: 3.7565x; 1.0205x over previous
#include <cuda_runtime.h>

#define NB    16
#define NN    4096
#define W     1024
#define MAXP  300
#define IOU_T 0.7f
#define SC_T  0.5f
#define SENT  0xFF800000u
#define FULLM 0xffffffffu

typedef unsigned long long ull;

// Inter-kernel scratch (static __device__: no allocation)
__device__ ull      g_keys[NB][NN];
__device__ float4   g_box [NB][W];
__device__ float    g_area[NB][W];
__device__ unsigned g_mask[NB][W][32];   // row i, word w -> suppress bits j=w*32+b

// Exact fdiv_rn(inter,denom) >= 0.7 via guard band (2e-6 rel >> accumulated
// <=3*2^-24 rounding); exact division only inside the band.
__device__ __forceinline__ bool iou_ge(float4 a, float aa, float4 b, float ab) {
    float xx1 = fmaxf(a.x, b.x);
    float yy1 = fmaxf(a.y, b.y);
    float xx2 = fminf(a.z, b.z);
    float yy2 = fminf(a.w, b.w);
    float w = fmaxf(__fadd_rn(xx2, -xx1), 0.0f);
    float h = fmaxf(__fadd_rn(yy2, -yy1), 0.0f);
    float inter = __fmul_rn(w, h);
    float denom = __fadd_rn(__fadd_rn(aa, ab), -inter);
    float td = __fmul_rn(IOU_T, denom);
    if (inter > __fmul_rn(td, 1.000002f)) return true;
    if (inter < __fmul_rn(td, 0.999998f)) return false;
    return __fdiv_rn(inter, denom) >= IOU_T;
}

// ---------------- K1: register/shfl bitonic sort (4 keys/thread) -----------
__global__ __launch_bounds__(1024, 1)
void k_sort(const float4* __restrict__ props, const float2* __restrict__ cls)
{
    __shared__ ull sh[NN];
    const int b = blockIdx.x;
    const int t = threadIdx.x;
    const float4* C4 = (const float4*)(cls + (size_t)b * NN);
    const float4* P  = props + (size_t)b * NN;

    // keys: descending score, ascending index, invalid (<=0.5) last
    float4 a0 = C4[2 * t], a1 = C4[2 * t + 1];
    float sc[4] = { a0.y, a0.w, a1.y, a1.w };
    ull v[4];
    #pragma unroll
    for (int e = 0; e < 4; ++e) {
        unsigned u = (sc[e] > SC_T) ? ~(__float_as_uint(sc[e]) | 0x80000000u) : SENT;
        v[e] = ((ull)u << 32) | (unsigned)(4 * t + e);
    }

    for (int k = 2; k <= NN; k <<= 1) {
        for (int j = k >> 1; j > 0; j >>= 1) {
            if (j >= 128) {                       // cross-warp: via smem
                #pragma unroll
                for (int e = 0; e < 4; ++e) sh[4 * t + e] = v[e];
                __syncthreads();
                #pragma unroll
                for (int e = 0; e < 4; ++e) {
                    int idx = 4 * t + e;
                    ull p = sh[idx ^ j];
                    bool up    = ((idx & k) == 0);
                    bool lower = ((idx & j) == 0);
                    ull mn = (v[e] < p) ? v[e] : p;
                    ull mx = (v[e] < p) ? p : v[e];
                    v[e] = (up == lower) ? mn : mx;
                }
                __syncthreads();
            } else if (j >= 4) {                  // in-warp: shfl.bfly
                int m = j >> 2;
                bool lower = ((t & m) == 0);
                #pragma unroll
                for (int e = 0; e < 4; ++e) {
                    int idx = 4 * t + e;
                    ull p = __shfl_xor_sync(FULLM, v[e], m);
                    bool up = ((idx & k) == 0);
                    ull mn = (v[e] < p) ? v[e] : p;
                    ull mx = (v[e] < p) ? p : v[e];
                    v[e] = (up == lower) ? mn : mx;
                }
            } else if (j == 2) {                  // in-registers
                #pragma unroll
                for (int e = 0; e < 2; ++e) {
                    bool up = (((4 * t + e) & k) == 0);
                    if ((v[e] > v[e + 2]) == up) { ull tmp = v[e]; v[e] = v[e + 2]; v[e + 2] = tmp; }
                }
            } else {                              // j == 1
                #pragma unroll
                for (int e = 0; e < 4; e += 2) {
                    bool up = (((4 * t + e) & k) == 0);
                    if ((v[e] > v[e + 1]) == up) { ull tmp = v[e]; v[e] = v[e + 1]; v[e + 1] = tmp; }
                }
            }
        }
    }

    #pragma unroll
    for (int e = 0; e < 4; ++e) g_keys[b][4 * t + e] = v[e];
    if (t < 256) {                                // window gather (idx < 1024)
        #pragma unroll
        for (int e = 0; e < 4; ++e) {
            int idx = 4 * t + e;
            int oi  = (int)(v[e] & 0xffffffffu);
            float4 p = P[oi];
            g_box[b][idx]  = p;
            g_area[b][idx] = __fmul_rn(__fadd_rn(p.z, -p.x), __fadd_rn(p.w, -p.y));
        }
    }
}

// ---------------- K2: suppression bit-matrix (16 images x 8 slices) --------
__global__ __launch_bounds__(1024, 1)
void k_mask()
{
    __shared__ float4 sb[W];
    __shared__ float  sa[W];
    const int b   = blockIdx.x;
    const int s   = blockIdx.y;
    const int tid = threadIdx.x;

    for (int t = tid; t < W; t += 1024) { sb[t] = g_box[b][t]; sa[t] = g_area[b][t]; }
    __syncthreads();

    const int r  = tid >> 3;
    const int wq = tid & 7;
    const int i  = ((r >> 4) * 8 + s) * 16 + (r & 15);
    const float4 bi = sb[i];
    const float  ai = sa[i];
    const int wlo = i >> 5;

    #pragma unroll
    for (int p = 0; p < 4; ++p) {
        int w = wq * 4 + p;
        unsigned bits = 0;
        if (w >= wlo) {
            #pragma unroll 8
            for (int bb = 0; bb < 32; ++bb) {
                int j = w * 32 + bb;
                if (iou_ge(bi, ai, sb[j], sa[j])) bits |= 1u << bb;
            }
            if (w == wlo) bits &= ~((2u << (i & 31)) - 1);   // only j > i
        }
        g_mask[b][i][w] = bits;
    }
}

// ---------------- K3: short-chain warp scan + rare exact fallback ----------
__global__ __launch_bounds__(1024, 1)
void k_scan(const float4* __restrict__ props, const float2* __restrict__ cls,
            float* __restrict__ outb, float* __restrict__ outs)
{
    extern __shared__ unsigned char sm[];
    unsigned* s_mask = (unsigned*)sm;                      // 131072 B
    ull*      s_sk   = (ull*)   (sm + 131072);             //   8192 B (window keys)
    float4*   s_box  = (float4*)(sm + 139264);             //  16384 B
    float*    s_area = (float*) (sm + 155648);             //   4096 B
    float4*   s_kbox = (float4*)(sm + 159744);             //   4800 B
    float*    s_kar  = (float*) (sm + 164544);             //   1200 B
    int*      s_kept = (int*)   (sm + 165744);             //   1200 B (ORIGINAL idx)
    unsigned* s_inv  = (unsigned*)(sm + 166944);           //    128 B
    int*      s_ctl  = (int*)   (sm + 167072);
    // fallback chunk arrays alias finished mask region
    float4*        c_box  = (float4*)sm;                   // 16384 B
    float*         c_area = (float*)(sm + 16384);          //  4096 B
    int*           c_oi   = (int*)  (sm + 20480);          //  4096 B
    unsigned char* c_sup  = (unsigned char*)(sm + 24576);  //  1024 B

    const int b   = blockIdx.x;
    const int tid = threadIdx.x;
    const int lane = tid & 31, wid = tid >> 5;
    const float4* P = props + (size_t)b * NN;
    const float2* C = cls   + (size_t)b * NN;

    // stage mask + window keys/boxes
    {
        const uint4* gm = (const uint4*)g_mask[b];
        uint4* smv = (uint4*)s_mask;
        for (int i = tid; i < 8192; i += 1024) smv[i] = gm[i];
        s_sk[tid]   = g_keys[b][tid];
        s_box[tid]  = g_box[b][tid];
        s_area[tid] = g_area[b][tid];
    }
    __syncthreads();
    {
        bool iv = ((unsigned)(s_sk[tid] >> 32) == SENT);
        unsigned bal = __ballot_sync(FULLM, iv);
        if (lane == 0) s_inv[wid] = bal;
    }
    __syncthreads();

    // ---- warp 0: greedy scan; chain = one broadcast LDS + AND + FFS ----
    if (tid < 32) {
        unsigned r = s_inv[lane];       // lane owns removed word `lane`
        int nk = 0; bool done = false;
        for (int blk = 0; blk < 32 && !done; ++blk) {
            unsigned alive = ~__shfl_sync(FULLM, r, blk);
            while (alive) {
                int t2 = __ffs(alive) - 1;
                int i  = blk * 32 + t2;
                if (lane == 0) s_kept[nk] = (int)(s_sk[i] & 0xffffffffu);
                nk++;
                if (nk == MAXP) { done = true; break; }
                r |= s_mask[i * 32 + lane];          // off critical chain
                unsigned roww = s_mask[i * 32 + blk]; // broadcast, on chain
                alive &= ~roww;
                alive &= ~(1u << t2);
            }
        }
        if (lane == 0) s_ctl[0] = nk;
    }
    __syncthreads();

    // ---- exact fallback beyond window (rare; uniform branch) ----
    if (s_ctl[0] < MAXP) {
        {
            int nk0 = s_ctl[0];
            for (int t = tid; t < nk0; t += 1024) {
                int oi = s_kept[t];
                float4 p = P[oi];
                s_kbox[t] = p;
                s_kar[t]  = __fmul_rn(__fadd_rn(p.z, -p.x), __fadd_rn(p.w, -p.y));
            }
        }
        __syncthreads();
        for (int c = 1; c < 4; ++c) {
            int nkc = s_ctl[0];
            if (nkc >= MAXP) break;
            {
                int jg = c * 1024 + tid;
                ull key = g_keys[b][jg];
                int oi = (int)(key & 0xffffffffu);
                float4 pb = P[oi];
                float  pa = __fmul_rn(__fadd_rn(pb.z, -pb.x), __fadd_rn(pb.w, -pb.y));
                unsigned char sp = ((unsigned)(key >> 32) == SENT) ? 1 : 0;
                if (!sp) {
                    for (int k2 = 0; k2 < nkc; ++k2)
                        if (iou_ge(s_kbox[k2], s_kar[k2], pb, pa)) { sp = 1; break; }
                }
                c_box[tid] = pb; c_area[tid] = pa; c_oi[tid] = oi; c_sup[tid] = sp;
            }
            __syncthreads();
            if (tid < 32) {
                unsigned supm = 0;
                for (int w = 0; w < 32; ++w)
                    supm |= (unsigned)c_sup[w * 32 + lane] << w;
                int nk = nkc; bool done2 = false;
                for (int blk = 0; blk < 32 && !done2; ++blk) {
                    unsigned alive = __ballot_sync(FULLM, !((supm >> blk) & 1));
                    while (alive) {
                        int t2 = __ffs(alive) - 1;
                        int li = blk * 32 + t2;
                        float4 bb = c_box[li]; float ba = c_area[li];
                        if (lane == 0) {
                            s_kept[nk] = c_oi[li];
                            s_kbox[nk] = bb; s_kar[nk] = ba;
                        }
                        nk++;
                        if (nk == MAXP) { done2 = true; break; }
                        for (int w = blk; w < 32; ++w) {
                            int j = w * 32 + lane;
                            if (j > li && !((supm >> w) & 1)) {
                                if (iou_ge(bb, ba, c_box[j], c_area[j])) supm |= 1u << w;
                            }
                        }
                        alive &= ~(1u << t2);
                        alive &= __ballot_sync(FULLM, !((supm >> blk) & 1));
                    }
                }
                if (lane == 0) s_ctl[0] = nk;
            }
            __syncthreads();
        }
    }
    __syncthreads();

    // ---- emit: kept original indices; pad = last kept (nk==0 -> order[N-1]) ----
    {
        int nk = s_ctl[0];
        int pad_oi = (nk > 0) ? s_kept[nk - 1]
                              : (int)(g_keys[b][NN - 1] & 0xffffffffu);
        for (int t = tid; t < MAXP; t += 1024) {
            int oi = (t < nk) ? s_kept[t] : pad_oi;
            reinterpret_cast<float4*>(outb)[b * MAXP + t] = P[oi];
            outs[b * MAXP + t] = C[oi].y;
        }
    }
}

extern "C" void kernel_launch(void* const* d_in, const int* in_sizes, int n_in,
                              void* d_out, int out_size)
{
    const float4* props = (const float4*)d_in[0];
    const float2* cls   = (const float2*)d_in[1];
    float* outb = (float*)d_out;                          // [16,300,4]
    float* outs = (float*)d_out + NB * MAXP * 4;          // [16,300]

    static int smem_set = 0;
    const int K3_SMEM = 167104;
    if (!smem_set) {
        cudaFuncSetAttribute(k_scan, cudaFuncAttributeMaxDynamicSharedMemorySize, K3_SMEM);
        smem_set = 1;
    }
    k_sort<<<NB, 1024>>>(props, cls);
    k_mask<<<dim3(NB, 8), 1024>>>();
    k_scan<<<NB, 1024, K3_SMEM>>>(props, cls, outb, outs);
}

// round 5
// speedup vs baseline: 5.7261x; 1.5243x over previous
#include <cuda_runtime.h>

#define NB    16
#define NN    4096
#define W     1024
#define MAXP  300
#define IOU_T 0.7f
#define SC_T  0.5f
#define SENT  0xFF800000u
#define FULLM 0xffffffffu

typedef unsigned long long ull;

// Inter-kernel scratch (static __device__: no allocation)
__device__ ull      g_runs [NB][NN];     // sorted 1024-chunks
__device__ ull      g_runs2[NB][NN];     // sorted 2048-runs
__device__ ull      g_keys [NB][NN];     // fully sorted
__device__ float4   g_box  [NB][W];
__device__ float    g_area [NB][W];
__device__ unsigned g_mask [NB][W][32];  // row i, word w -> suppress bits j=w*32+b

// Exact fdiv_rn(inter,denom) >= 0.7 via guard band (2e-6 rel >> accumulated
// <=3*2^-24 rounding); exact division only inside the band.
__device__ __forceinline__ bool iou_ge(float4 a, float aa, float4 b, float ab) {
    float xx1 = fmaxf(a.x, b.x);
    float yy1 = fmaxf(a.y, b.y);
    float xx2 = fminf(a.z, b.z);
    float yy2 = fminf(a.w, b.w);
    float w = fmaxf(__fadd_rn(xx2, -xx1), 0.0f);
    float h = fmaxf(__fadd_rn(yy2, -yy1), 0.0f);
    float inter = __fmul_rn(w, h);
    float denom = __fadd_rn(__fadd_rn(aa, ab), -inter);
    float td = __fmul_rn(IOU_T, denom);
    if (inter > __fmul_rn(td, 1.000002f)) return true;
    if (inter < __fmul_rn(td, 0.999998f)) return false;
    return __fdiv_rn(inter, denom) >= IOU_T;
}

// ---------------- K1a: sort 1024-chunks (16 images x 4 chunks) -------------
__global__ __launch_bounds__(256, 1)
void k_sort1(const float2* __restrict__ cls)
{
    __shared__ ull sh[1024];
    const int b = blockIdx.x, c = blockIdx.y, t = threadIdx.x;
    const float4* C4 = (const float4*)(cls + (size_t)b * NN) + c * 512;

    float4 a0 = C4[2 * t], a1 = C4[2 * t + 1];
    float sc[4] = { a0.y, a0.w, a1.y, a1.w };
    ull v[4];
    #pragma unroll
    for (int e = 0; e < 4; ++e) {
        unsigned u = (sc[e] > SC_T) ? ~(__float_as_uint(sc[e]) | 0x80000000u) : SENT;
        v[e] = ((ull)u << 32) | (unsigned)(c * 1024 + 4 * t + e);
    }

    for (int k = 2; k <= 1024; k <<= 1) {
        for (int j = k >> 1; j > 0; j >>= 1) {
            if (j >= 128) {                       // cross-warp-span via smem
                #pragma unroll
                for (int e = 0; e < 4; ++e) sh[4 * t + e] = v[e];
                __syncthreads();
                #pragma unroll
                for (int e = 0; e < 4; ++e) {
                    int idx = 4 * t + e;
                    ull p = sh[idx ^ j];
                    bool up    = ((idx & k) == 0);
                    bool lower = ((idx & j) == 0);
                    ull mn = (v[e] < p) ? v[e] : p;
                    ull mx = (v[e] < p) ? p : v[e];
                    v[e] = (up == lower) ? mn : mx;
                }
                __syncthreads();
            } else if (j >= 4) {                  // in-warp shfl.bfly
                int m = j >> 2;
                bool lower = ((t & m) == 0);
                #pragma unroll
                for (int e = 0; e < 4; ++e) {
                    int idx = 4 * t + e;
                    ull p = __shfl_xor_sync(FULLM, v[e], m);
                    bool up = ((idx & k) == 0);
                    ull mn = (v[e] < p) ? v[e] : p;
                    ull mx = (v[e] < p) ? p : v[e];
                    v[e] = (up == lower) ? mn : mx;
                }
            } else if (j == 2) {
                #pragma unroll
                for (int e = 0; e < 2; ++e) {
                    bool up = (((4 * t + e) & k) == 0);
                    if ((v[e] > v[e + 2]) == up) { ull tmp = v[e]; v[e] = v[e + 2]; v[e + 2] = tmp; }
                }
            } else {
                #pragma unroll
                for (int e = 0; e < 4; e += 2) {
                    bool up = (((4 * t + e) & k) == 0);
                    if ((v[e] > v[e + 1]) == up) { ull tmp = v[e]; v[e] = v[e + 1]; v[e + 1] = tmp; }
                }
            }
        }
    }

    #pragma unroll
    for (int e = 0; e < 4; ++e) g_runs[b][c * 1024 + 4 * t + e] = v[e];
}

// merge-path: emit 4 outputs starting at rank r of merge(A[0:n], B[0:m]).
// Keys unique -> deterministic, equals monolithic sort order.
__device__ __forceinline__ void merge4(const ull* __restrict__ A, int n,
                                       const ull* __restrict__ B, int m,
                                       int r, ull* o)
{
    int lo = max(0, r - m), hi = min(r, n);
    while (lo < hi) {
        int mid = (lo + hi) >> 1;
        if (A[mid] <= B[r - 1 - mid]) lo = mid + 1; else hi = mid;
    }
    int a = lo, bb = r - lo;
    #pragma unroll
    for (int e = 0; e < 4; ++e) {
        bool ta = (bb >= m) || (a < n && A[a] < B[bb]);
        o[e] = ta ? A[a++] : B[bb++];
    }
}

// ---------------- K1b: merge 1024+1024 -> 2048 (16 x 2) --------------------
__global__ __launch_bounds__(512, 1)
void k_merge2()
{
    __shared__ ull sA[1024], sB[1024];
    const int b = blockIdx.x, p = blockIdx.y, t = threadIdx.x;
    const ull* G = g_runs[b] + p * 2048;
    sA[t] = G[t];          sA[t + 512] = G[t + 512];
    sB[t] = G[1024 + t];   sB[t + 512] = G[1536 + t];
    __syncthreads();
    ull o[4];
    merge4(sA, 1024, sB, 1024, 4 * t, o);
    #pragma unroll
    for (int e = 0; e < 4; ++e) g_runs2[b][p * 2048 + 4 * t + e] = o[e];
}

// ---------------- K1c: merge 2048+2048 -> 4096 + window gather -------------
__global__ __launch_bounds__(1024, 1)
void k_merge4(const float4* __restrict__ props)
{
    __shared__ ull sA[2048], sB[2048];
    const int b = blockIdx.x, t = threadIdx.x;
    const float4* P = props + (size_t)b * NN;
    sA[t] = g_runs2[b][t];          sA[t + 1024] = g_runs2[b][t + 1024];
    sB[t] = g_runs2[b][2048 + t];   sB[t + 1024] = g_runs2[b][3072 + t];
    __syncthreads();
    ull o[4];
    merge4(sA, 2048, sB, 2048, 4 * t, o);
    #pragma unroll
    for (int e = 0; e < 4; ++e) {
        int r = 4 * t + e;
        g_keys[b][r] = o[e];
        if (r < W) {
            int oi = (int)(o[e] & 0xffffffffu);
            float4 p = P[oi];
            g_box[b][r]  = p;
            g_area[b][r] = __fmul_rn(__fadd_rn(p.z, -p.x), __fadd_rn(p.w, -p.y));
        }
    }
}

// ---------------- K2: bit-matrix, warp-per-row + ballot (16 x 8) -----------
__global__ __launch_bounds__(1024, 1)
void k_mask()
{
    const int b    = blockIdx.x;
    const int s    = blockIdx.y;                 // 0..7
    const int lane = threadIdx.x & 31;
    const int wid  = threadIdx.x >> 5;           // 0..31

    #pragma unroll
    for (int rr = 0; rr < 4; ++rr) {
        const int i = (wid * 4 + rr) * 8 + s;    // rows ≡ s (mod 8): balanced
        const float4 bi = __ldg(&g_box[b][i]);
        const float  ai = __ldg(&g_area[b][i]);
        const int wlo = i >> 5;
        for (int w = 0; w < 32; ++w) {
            unsigned bits = 0;
            if (w >= wlo) {                      // uniform per warp
                int j = w * 32 + lane;
                float4 bj = __ldg(&g_box[b][j]);
                float  aj = __ldg(&g_area[b][j]);
                bool sup = (j > i) && iou_ge(bi, ai, bj, aj);
                bits = __ballot_sync(FULLM, sup);
            }
            if (lane == 0) g_mask[b][i][w] = bits;
        }
    }
}

// ---------------- K3: short-chain warp scan + rare exact fallback ----------
__global__ __launch_bounds__(1024, 1)
void k_scan(const float4* __restrict__ props, const float2* __restrict__ cls,
            float* __restrict__ outb, float* __restrict__ outs)
{
    extern __shared__ unsigned char sm[];
    unsigned* s_mask = (unsigned*)sm;                      // 131072 B
    ull*      s_sk   = (ull*)   (sm + 131072);             //   8192 B
    float4*   s_box  = (float4*)(sm + 139264);             //  16384 B
    float*    s_area = (float*) (sm + 155648);             //   4096 B
    float4*   s_kbox = (float4*)(sm + 159744);             //   4800 B
    float*    s_kar  = (float*) (sm + 164544);             //   1200 B
    int*      s_kept = (int*)   (sm + 165744);             //   1200 B (ORIGINAL idx)
    unsigned* s_inv  = (unsigned*)(sm + 166944);           //    128 B
    int*      s_ctl  = (int*)   (sm + 167072);
    // fallback chunk arrays alias finished mask region
    float4*        c_box  = (float4*)sm;                   // 16384 B
    float*         c_area = (float*)(sm + 16384);          //  4096 B
    int*           c_oi   = (int*)  (sm + 20480);          //  4096 B
    unsigned char* c_sup  = (unsigned char*)(sm + 24576);  //  1024 B

    const int b   = blockIdx.x;
    const int tid = threadIdx.x;
    const int lane = tid & 31, wid = tid >> 5;
    const float4* P = props + (size_t)b * NN;
    const float2* C = cls   + (size_t)b * NN;

    {
        const uint4* gm = (const uint4*)g_mask[b];
        uint4* smv = (uint4*)s_mask;
        for (int i = tid; i < 8192; i += 1024) smv[i] = gm[i];
        s_sk[tid]   = g_keys[b][tid];
        s_box[tid]  = g_box[b][tid];
        s_area[tid] = g_area[b][tid];
    }
    __syncthreads();
    {
        bool iv = ((unsigned)(s_sk[tid] >> 32) == SENT);
        unsigned bal = __ballot_sync(FULLM, iv);
        if (lane == 0) s_inv[wid] = bal;
    }
    __syncthreads();

    // ---- warp 0: greedy scan; chain = one broadcast LDS + AND + FFS ----
    if (tid < 32) {
        unsigned r = s_inv[lane];
        int nk = 0; bool done = false;
        for (int blk = 0; blk < 32 && !done; ++blk) {
            unsigned alive = ~__shfl_sync(FULLM, r, blk);
            while (alive) {
                int t2 = __ffs(alive) - 1;
                int i  = blk * 32 + t2;
                if (lane == 0) s_kept[nk] = (int)(s_sk[i] & 0xffffffffu);
                nk++;
                if (nk == MAXP) { done = true; break; }
                r |= s_mask[i * 32 + lane];           // off critical chain
                unsigned roww = s_mask[i * 32 + blk]; // broadcast, on chain
                alive &= ~roww;
                alive &= ~(1u << t2);
            }
        }
        if (lane == 0) s_ctl[0] = nk;
    }
    __syncthreads();

    // ---- exact fallback beyond window (rare; uniform branch) ----
    if (s_ctl[0] < MAXP) {
        {
            int nk0 = s_ctl[0];
            for (int t = tid; t < nk0; t += 1024) {
                int oi = s_kept[t];
                float4 p = P[oi];
                s_kbox[t] = p;
                s_kar[t]  = __fmul_rn(__fadd_rn(p.z, -p.x), __fadd_rn(p.w, -p.y));
            }
        }
        __syncthreads();
        for (int c = 1; c < 4; ++c) {
            int nkc = s_ctl[0];
            if (nkc >= MAXP) break;
            {
                int jg = c * 1024 + tid;
                ull key = g_keys[b][jg];
                int oi = (int)(key & 0xffffffffu);
                float4 pb = P[oi];
                float  pa = __fmul_rn(__fadd_rn(pb.z, -pb.x), __fadd_rn(pb.w, -pb.y));
                unsigned char sp = ((unsigned)(key >> 32) == SENT) ? 1 : 0;
                if (!sp) {
                    for (int k2 = 0; k2 < nkc; ++k2)
                        if (iou_ge(s_kbox[k2], s_kar[k2], pb, pa)) { sp = 1; break; }
                }
                c_box[tid] = pb; c_area[tid] = pa; c_oi[tid] = oi; c_sup[tid] = sp;
            }
            __syncthreads();
            if (tid < 32) {
                unsigned supm = 0;
                for (int w = 0; w < 32; ++w)
                    supm |= (unsigned)c_sup[w * 32 + lane] << w;
                int nk = nkc; bool done2 = false;
                for (int blk = 0; blk < 32 && !done2; ++blk) {
                    unsigned alive = __ballot_sync(FULLM, !((supm >> blk) & 1));
                    while (alive) {
                        int t2 = __ffs(alive) - 1;
                        int li = blk * 32 + t2;
                        float4 bb = c_box[li]; float ba = c_area[li];
                        if (lane == 0) {
                            s_kept[nk] = c_oi[li];
                            s_kbox[nk] = bb; s_kar[nk] = ba;
                        }
                        nk++;
                        if (nk == MAXP) { done2 = true; break; }
                        for (int w = blk; w < 32; ++w) {
                            int j = w * 32 + lane;
                            if (j > li && !((supm >> w) & 1)) {
                                if (iou_ge(bb, ba, c_box[j], c_area[j])) supm |= 1u << w;
                            }
                        }
                        alive &= ~(1u << t2);
                        alive &= __ballot_sync(FULLM, !((supm >> blk) & 1));
                    }
                }
                if (lane == 0) s_ctl[0] = nk;
            }
            __syncthreads();
        }
    }
    __syncthreads();

    // ---- emit ----
    {
        int nk = s_ctl[0];
        int pad_oi = (nk > 0) ? s_kept[nk - 1]
                              : (int)(g_keys[b][NN - 1] & 0xffffffffu);
        for (int t = tid; t < MAXP; t += 1024) {
            int oi = (t < nk) ? s_kept[t] : pad_oi;
            reinterpret_cast<float4*>(outb)[b * MAXP + t] = P[oi];
            outs[b * MAXP + t] = C[oi].y;
        }
    }
}

extern "C" void kernel_launch(void* const* d_in, const int* in_sizes, int n_in,
                              void* d_out, int out_size)
{
    const float4* props = (const float4*)d_in[0];
    const float2* cls   = (const float2*)d_in[1];
    float* outb = (float*)d_out;                          // [16,300,4]
    float* outs = (float*)d_out + NB * MAXP * 4;          // [16,300]

    static int smem_set = 0;
    const int K3_SMEM = 167104;
    if (!smem_set) {
        cudaFuncSetAttribute(k_scan, cudaFuncAttributeMaxDynamicSharedMemorySize, K3_SMEM);
        smem_set = 1;
    }
    k_sort1 <<<dim3(NB, 4), 256>>>(cls);
    k_merge2<<<dim3(NB, 2), 512>>>();
    k_merge4<<<NB, 1024>>>(props);
    k_mask  <<<dim3(NB, 8), 1024>>>();
    k_scan  <<<NB, 1024, K3_SMEM>>>(props, cls, outb, outs);
}